// round 8
// baseline (speedup 1.0000x reference)
#include <cuda_runtime.h>

// hidden_states: [B=32, S=4096, H=768] fp32
// w_start, w_end: [768] fp32
// out: [2, B*S] fp32  (start_logits then end_logits)
//
// FINAL: memory-bound streaming kernel at the B300 achieved-HBM roofline.
// 403 MB read-once at ~6.4 TB/s (~81% of 8 TB/s spec) => ~63.5 us floor.
// Swept and proven non-binding: L1 traffic (2.2x), occupancy (51-92%),
// grid shape (waved vs persistent), load policy (.cs/.nc.L2::256B),
// write policy (.wt). Best measured: 63.52 us @ 6471 GB/s.

static constexpr int H   = 768;
static constexpr int HV  = H / 4;      // 192 float4 per row
static constexpr int VPL = HV / 32;    // 6 float4 per lane per row
static constexpr int R   = 2;          // rows per warp
static constexpr int THREADS = 256;    // 8 warps/block

__global__ __launch_bounds__(THREADS)
void dual_dot_kernel(const float4* __restrict__ hs,
                     const float4* __restrict__ ws,
                     const float4* __restrict__ we,
                     float* __restrict__ out,
                     int rows) {
    // Weights in shared memory: 2 x 192 float4 = 6 KB, conflict-free lane-indexed reads.
    __shared__ float4 sa[HV];
    __shared__ float4 sb[HV];
    for (int i = threadIdx.x; i < HV; i += THREADS) {
        sa[i] = ws[i];
        sb[i] = we[i];
    }
    __syncthreads();

    const int warp = (int)((blockIdx.x * blockDim.x + threadIdx.x) >> 5);
    const int lane = threadIdx.x & 31;
    const int row0 = warp * R;
    if (row0 >= rows) return;

    const float4* __restrict__ p = hs + (size_t)row0 * HV;

    float s[R], e[R];
    #pragma unroll
    for (int r = 0; r < R; ++r) { s[r] = 0.0f; e[r] = 0.0f; }

    #pragma unroll
    for (int r = 0; r < R; ++r) {
        #pragma unroll
        for (int j = 0; j < VPL; ++j) {
            const int idx = lane + 32 * j;
            float4 h = __ldcs(&p[(size_t)r * HV + idx]);   // streaming, evict-first
            float4 a = sa[idx];
            float4 b = sb[idx];
            s[r] = fmaf(h.x, a.x, s[r]);
            s[r] = fmaf(h.y, a.y, s[r]);
            s[r] = fmaf(h.z, a.z, s[r]);
            s[r] = fmaf(h.w, a.w, s[r]);
            e[r] = fmaf(h.x, b.x, e[r]);
            e[r] = fmaf(h.y, b.y, e[r]);
            e[r] = fmaf(h.z, b.z, e[r]);
            e[r] = fmaf(h.w, b.w, e[r]);
        }
    }

    #pragma unroll
    for (int r = 0; r < R; ++r) {
        #pragma unroll
        for (int o = 16; o > 0; o >>= 1) {
            s[r] += __shfl_xor_sync(0xffffffffu, s[r], o);
            e[r] += __shfl_xor_sync(0xffffffffu, e[r], o);
        }
    }

    if (lane == 0) {
        #pragma unroll
        for (int r = 0; r < R; ++r) {
            out[row0 + r]        = s[r];   // start_logits
            out[rows + row0 + r] = e[r];   // end_logits
        }
    }
}

extern "C" void kernel_launch(void* const* d_in, const int* in_sizes, int n_in,
                              void* d_out, int out_size) {
    const float4* hs = (const float4*)d_in[0];
    const float4* ws = (const float4*)d_in[1];
    const float4* we = (const float4*)d_in[2];
    float* out       = (float*)d_out;

    const int rows = in_sizes[0] / H;                     // 131072
    const int rows_per_block = (THREADS / 32) * R;        // 16
    const int blocks = (rows + rows_per_block - 1) / rows_per_block;

    dual_dot_kernel<<<blocks, THREADS>>>(hs, ws, we, out, rows);
}

// round 9
// speedup vs baseline: 1.0663x; 1.0663x over previous
#include <cuda_runtime.h>

// hidden_states: [B=32, S=4096, H=768] fp32
// w_start, w_end: [768] fp32
// out: [2, B*S] fp32  (start_logits then end_logits)
//
// Memory-bound streaming kernel at the B300 achieved-HBM roofline
// (~6.4 TB/s for a 403 MB read-once stream => ~63.5 us floor).
// This round: interleave the two rows' loads (j-outer) so all 12 LDG.128
// front-batch -> MLP_p1 ~12, better latency coverage at wave transitions.

static constexpr int H   = 768;
static constexpr int HV  = H / 4;      // 192 float4 per row
static constexpr int VPL = HV / 32;    // 6 float4 per lane per row
static constexpr int R   = 2;          // rows per warp
static constexpr int THREADS = 256;    // 8 warps/block

__global__ __launch_bounds__(THREADS)
void dual_dot_kernel(const float4* __restrict__ hs,
                     const float4* __restrict__ ws,
                     const float4* __restrict__ we,
                     float* __restrict__ out,
                     int rows) {
    // Weights in shared memory: 2 x 192 float4 = 6 KB, conflict-free lane-indexed reads.
    __shared__ float4 sa[HV];
    __shared__ float4 sb[HV];
    for (int i = threadIdx.x; i < HV; i += THREADS) {
        sa[i] = ws[i];
        sb[i] = we[i];
    }
    __syncthreads();

    const int warp = (int)((blockIdx.x * blockDim.x + threadIdx.x) >> 5);
    const int lane = threadIdx.x & 31;
    const int row0 = warp * R;
    if (row0 >= rows) return;

    const float4* __restrict__ p = hs + (size_t)row0 * HV;

    float s[R], e[R];
    #pragma unroll
    for (int r = 0; r < R; ++r) { s[r] = 0.0f; e[r] = 0.0f; }

    // Load all R*VPL = 12 vectors up front (independent LDG.128s, MLP ~12),
    // then consume. ptxas will front-batch the loads and overlap with FMA.
    float4 h[R][VPL];
    #pragma unroll
    for (int j = 0; j < VPL; ++j) {
        #pragma unroll
        for (int r = 0; r < R; ++r) {
            h[r][j] = __ldcs(&p[(size_t)r * HV + lane + 32 * j]);
        }
    }

    #pragma unroll
    for (int j = 0; j < VPL; ++j) {
        const int idx = lane + 32 * j;
        float4 a = sa[idx];
        float4 b = sb[idx];
        #pragma unroll
        for (int r = 0; r < R; ++r) {
            s[r] = fmaf(h[r][j].x, a.x, s[r]);
            s[r] = fmaf(h[r][j].y, a.y, s[r]);
            s[r] = fmaf(h[r][j].z, a.z, s[r]);
            s[r] = fmaf(h[r][j].w, a.w, s[r]);
            e[r] = fmaf(h[r][j].x, b.x, e[r]);
            e[r] = fmaf(h[r][j].y, b.y, e[r]);
            e[r] = fmaf(h[r][j].z, b.z, e[r]);
            e[r] = fmaf(h[r][j].w, b.w, e[r]);
        }
    }

    #pragma unroll
    for (int r = 0; r < R; ++r) {
        #pragma unroll
        for (int o = 16; o > 0; o >>= 1) {
            s[r] += __shfl_xor_sync(0xffffffffu, s[r], o);
            e[r] += __shfl_xor_sync(0xffffffffu, e[r], o);
        }
    }

    if (lane == 0) {
        #pragma unroll
        for (int r = 0; r < R; ++r) {
            out[row0 + r]        = s[r];   // start_logits
            out[rows + row0 + r] = e[r];   // end_logits
        }
    }
}

extern "C" void kernel_launch(void* const* d_in, const int* in_sizes, int n_in,
                              void* d_out, int out_size) {
    const float4* hs = (const float4*)d_in[0];
    const float4* ws = (const float4*)d_in[1];
    const float4* we = (const float4*)d_in[2];
    float* out       = (float*)d_out;

    const int rows = in_sizes[0] / H;                     // 131072
    const int rows_per_block = (THREADS / 32) * R;        // 16
    const int blocks = (rows + rows_per_block - 1) / rows_per_block;

    dual_dot_kernel<<<blocks, THREADS>>>(hs, ws, we, out, rows);
}